// round 16
// baseline (speedup 1.0000x reference)
#include <cuda_runtime.h>
#include <cuda_bf16.h>
#include <cuda.h>
#include <dlfcn.h>
#include <cstdint>
#include <cstdio>
#include <cstdlib>
#include <cstring>

// Problem constants
#define MDIM 8192
#define KDIM 4096
#define NDIM 4096

// SW128 swizzle (Swizzle<3,4,3>) on byte offsets
#define SWZ(o) ((o) ^ (((o) >> 3) & 0x70))

// Scratch (static __device__; no allocation anywhere).
// g_xb: quantized activations as bf16, 128(M)x64(K) tiles of 16KB, SW128
//   pre-swizzled. Tile (mt, kt) at ((mt*64 + kt) << 14).  64 MB.
// g_wb: weights (transposed to [N,K]) as bf16, same tiling. 32 MB.
__device__ __align__(1024) uint8_t g_xb[(size_t)MDIM * KDIM * 2];
__device__ __align__(1024) uint8_t g_wb[(size_t)NDIM * KDIM * 2];
__device__ float g_ascale[MDIM];
__device__ int   g_w_is_i32;
__device__ int   g_sb_swap;

// ===========================================================================
// Hand-written PTX (sm_103a, ISA 8.8) loaded via driver JIT.
// tcgen05 bf16 GEMM, cluster (1,2): the 2 CTAs of a pair share the same
// B tile (same ctaid.x). Each loads HALF the B chunk and multicasts it to
// both CTAs -> L2 B-traffic halved (3GB -> 2GB total reads).
// CTA tile 128(M) x 256(N), K-chunk 64 (4 x K=16 MMA), 4-stage pipeline,
// empty[] barriers count=2 + commit.multicast so neither producer overruns
// the peer consumer. Fused dequant epilogue.
// ===========================================================================
static const char* GEMM_PTX = R"PTX(
.version 8.8
.target sm_103a
.address_size 64

.extern .shared .align 1024 .b8 sm[];

.visible .entry gemm_tc(
    .param .u64 pA,
    .param .u64 pB,
    .param .u64 pASC,
    .param .u64 pC2,
    .param .u64 pC3,
    .param .u64 pSB,
    .param .u64 pOut
)
.reqntid 128, 1, 1
{
    .reg .pred %p<16>;
    .reg .b32 %r<64>;
    .reg .b64 %rd<64>;
    .reg .b32 %d<32>;
    .reg .b16 %hh<2>;
    .reg .f32 %w<4>;
    .reg .f32 %x<4>;
    .reg .f32 %fv<4>;
    .reg .f32 %fA;

    mov.u32 %r1, %tid.x;
    mov.u32 %r2, %ctaid.x;
    mov.u32 %r3, %ctaid.y;
    mov.u32 %r4, sm;
    shr.u32 %r5, %r1, 5;
    and.b32 %r6, %r1, 31;
    mov.u32 %r50, 0;
    mov.u16 %hh0, 3;

    // ---- TMEM alloc (warp 0 only) ----
    setp.ne.u32 %p1, %r5, 0;
    @%p1 bra LNOALLOC;
    mov.u32 %r26, 256;
    tcgen05.alloc.cta_group::1.sync.aligned.shared::cta.b32 [%r4], %r26;
    tcgen05.relinquish_alloc_permit.cta_group::1.sync.aligned;
LNOALLOC:

    // ---- barrier init (thread 0) ----
    // full[s] at sm+16+16s (count 1), empty[s] at sm+24+16s (count 2:
    // one commit.multicast arrival from EACH CTA of the pair), done at sm+96
    setp.ne.u32 %p2, %r1, 0;
    @%p2 bra LINIT_DONE;
    add.u32 %r7, %r4, 16;
    mbarrier.init.shared.b64 [%r7], 1;
    add.u32 %r7, %r4, 24;
    mbarrier.init.shared.b64 [%r7], 2;
    add.u32 %r7, %r4, 32;
    mbarrier.init.shared.b64 [%r7], 1;
    add.u32 %r7, %r4, 40;
    mbarrier.init.shared.b64 [%r7], 2;
    add.u32 %r7, %r4, 48;
    mbarrier.init.shared.b64 [%r7], 1;
    add.u32 %r7, %r4, 56;
    mbarrier.init.shared.b64 [%r7], 2;
    add.u32 %r7, %r4, 64;
    mbarrier.init.shared.b64 [%r7], 1;
    add.u32 %r7, %r4, 72;
    mbarrier.init.shared.b64 [%r7], 2;
    add.u32 %r7, %r4, 96;
    mbarrier.init.shared.b64 [%r7], 1;
LINIT_DONE:
    bar.sync 0;
    // cluster-wide: all mbarriers must be initialized before any peer
    // multicast (TMA complete_tx or commit) can target them.
    barrier.cluster.arrive.aligned;
    barrier.cluster.wait.aligned;
    ld.shared.b32 %r8, [%r4];

    setp.eq.u32 %p3, %r1, 0;
    @!%p3 bra LCHK_PROD;

    // ================= MMA issuer (tid 0) =================
    mov.u32 %r10, 0;          // kt
    mov.u32 %r11, 0;          // phase
    mov.u64 %rd6, 0x4000404000010000;   // SW128 K-major desc base (SBO=64, LBO=1)
    mov.u32 %r20, 0x08400490;           // idesc: F32, BF16xBF16, M=128, N=256
    setp.eq.u32 %p6, %r50, 0;           // always-true (accumulate)
LMMA_LOOP:
    and.b32 %r12, %r10, 3;
    shl.b32 %r13, %r12, 4;
    add.u32 %r14, %r4, 16;
    add.u32 %r14, %r14, %r13;           // full[s]
LMMA_WAIT:
    mbarrier.try_wait.parity.shared.b64 %p4, [%r14], %r11;
    @!%p4 bra LMMA_WAIT;

    mul.lo.u32 %r15, %r12, 49152;
    add.u32 %r16, %r4, 1024;
    add.u32 %r16, %r16, %r15;           // stage base (A)
    shr.u32 %r17, %r16, 4;
    and.b32 %r17, %r17, 16383;
    cvt.u64.u32 %rd7, %r17;
    or.b64 %rd8, %rd6, %rd7;            // A desc
    add.u32 %r18, %r16, 16384;          // B (32KB, two 128-row tiles)
    shr.u32 %r19, %r18, 4;
    and.b32 %r19, %r19, 16383;
    cvt.u64.u32 %rd9, %r19;
    or.b64 %rd10, %rd6, %rd9;           // B desc

    // 4 MMAs of K=16 bf16 (desc step = 2 x 16B = 32B = 16 bf16)
    setp.ne.u32 %p5, %r10, 0;
    tcgen05.mma.cta_group::1.kind::f16 [%r8], %rd8, %rd10, %r20, {%r50,%r50,%r50,%r50}, %p5;
    add.u64 %rd11, %rd8, 2;
    add.u64 %rd12, %rd10, 2;
    tcgen05.mma.cta_group::1.kind::f16 [%r8], %rd11, %rd12, %r20, {%r50,%r50,%r50,%r50}, %p6;
    add.u64 %rd11, %rd8, 4;
    add.u64 %rd12, %rd10, 4;
    tcgen05.mma.cta_group::1.kind::f16 [%r8], %rd11, %rd12, %r20, {%r50,%r50,%r50,%r50}, %p6;
    add.u64 %rd11, %rd8, 6;
    add.u64 %rd12, %rd10, 6;
    tcgen05.mma.cta_group::1.kind::f16 [%r8], %rd11, %rd12, %r20, {%r50,%r50,%r50,%r50}, %p6;

    setp.eq.u32 %p7, %r10, 63;
    add.u32 %r21, %r14, 8;              // empty[s]
    @%p7 bra LCOMMIT_LAST;
    // signal stage-empty to BOTH CTAs of the pair (each empty[] needs 2)
    tcgen05.commit.cta_group::1.mbarrier::arrive::one.shared::cluster.multicast::cluster.b64 [%r21], %hh0;
    bra LCOMMIT_END;
LCOMMIT_LAST:
    add.u32 %r22, %r4, 96;              // done (local only)
    tcgen05.commit.cta_group::1.mbarrier::arrive::one.shared::cluster.b64 [%r22];
LCOMMIT_END:

    setp.eq.u32 %p8, %r12, 3;
    xor.b32 %r24, %r11, 1;
    selp.b32 %r11, %r24, %r11, %p8;
    add.u32 %r10, %r10, 1;
    setp.lt.u32 %p9, %r10, 64;
    @%p9 bra LMMA_LOOP;
    bra LEPI;

LCHK_PROD:
    setp.eq.u32 %p3, %r1, 32;
    @!%p3 bra LEPI;

    // ================= producer (tid 32) =================
    ld.param.u64 %rd1, [pA];
    ld.param.u64 %rd2, [pB];
    cvt.u64.u32 %rd20, %r3;
    mul.lo.u64 %rd21, %rd20, 1048576;   // A CTA base: mt * 64 tiles * 16KB
    add.u64 %rd22, %rd1, %rd21;
    cvt.u64.u32 %rd23, %r2;
    mul.lo.u64 %rd24, %rd23, 2097152;   // B pair base: nt256 * 2 * 64 * 16KB
    add.u64 %rd25, %rd2, %rd24;
    // my half of B: rank r loads tile row (2*nt + r)
    mov.u32 %r55, %cluster_ctarank;
    cvt.u64.u32 %rd51, %r55;
    mul.lo.u64 %rd52, %rd51, 1048576;
    add.u64 %rd25, %rd25, %rd52;
    shl.b32 %r56, %r55, 14;             // rank * 16384
    add.u32 %r56, %r56, 16384;          // dst offset of my B half in stage
    mov.u32 %r10, 0;
    mov.u32 %r11, 1;
    mov.u32 %r25, 16384;
    mov.u32 %r27, 49152;
LPROD_LOOP:
    and.b32 %r12, %r10, 3;
    shl.b32 %r13, %r12, 4;
    add.u32 %r14, %r4, 24;
    add.u32 %r14, %r14, %r13;           // empty[s]
LPROD_WAIT:
    mbarrier.try_wait.parity.shared.b64 %p4, [%r14], %r11;
    @!%p4 bra LPROD_WAIT;
    sub.u32 %r15, %r14, 8;              // full[s]
    mbarrier.arrive.expect_tx.shared.b64 %rd40, [%r15], %r27;
    mul.lo.u32 %r16, %r12, 49152;
    add.u32 %r17, %r4, 1024;
    add.u32 %r17, %r17, %r16;
    cvt.u64.u32 %rd26, %r10;
    shl.b64 %rd27, %rd26, 14;           // kt * 16KB
    // A chunk: local only
    add.u64 %rd28, %rd22, %rd27;
    cp.async.bulk.shared::cta.global.mbarrier::complete_tx::bytes [%r17], [%rd28], %r25, [%r15];
    // my B half: multicast to both CTAs of the pair
    add.u64 %rd29, %rd25, %rd27;
    add.u32 %r18, %r17, %r56;
    cp.async.bulk.shared::cluster.global.mbarrier::complete_tx::bytes.multicast::cluster [%r18], [%rd29], %r25, [%r15], %hh0;
    setp.eq.u32 %p8, %r12, 3;
    xor.b32 %r24, %r11, 1;
    selp.b32 %r11, %r24, %r11, %p8;
    add.u32 %r10, %r10, 1;
    setp.lt.u32 %p9, %r10, 64;
    @%p9 bra LPROD_LOOP;

LEPI:
    add.u32 %r30, %r4, 96;
    mov.u32 %r31, 0;
LEPI_WAIT:
    mbarrier.try_wait.parity.shared.b64 %p4, [%r30], %r31;
    @!%p4 bra LEPI_WAIT;
    tcgen05.fence::after_thread_sync;

    // global row = ctaid.y*128 + wid*32 + lane
    shl.b32 %r32, %r3, 7;
    shl.b32 %r33, %r5, 5;
    add.u32 %r32, %r32, %r33;
    add.u32 %r32, %r32, %r6;
    cvt.u64.u32 %rd42, %r32;

    // as = ascale[row]
    ld.param.u64 %rd41, [pASC];
    cvta.to.global.u64 %rd41, %rd41;
    shl.b64 %rd43, %rd42, 2;
    add.u64 %rd41, %rd41, %rd43;
    ld.global.nc.f32 %fA, [%rd41];

    // resolve ws/bias pointers (sb_swap flag in device global)
    ld.param.u64 %rd45, [pC2];
    ld.param.u64 %rd46, [pC3];
    ld.param.u64 %rd44, [pSB];
    cvta.to.global.u64 %rd44, %rd44;
    ld.global.u32 %r34, [%rd44];
    setp.ne.u32 %p10, %r34, 0;
    selp.b64 %rd47, %rd46, %rd45, %p10;   // wscale
    selp.b64 %rd48, %rd45, %rd46, %p10;   // bias
    cvta.to.global.u64 %rd47, %rd47;
    cvta.to.global.u64 %rd48, %rd48;
    cvt.u64.u32 %rd34, %r2;
    shl.b64 %rd35, %rd34, 10;             // ctaid.x * 256 cols * 4B
    add.u64 %rd47, %rd47, %rd35;
    add.u64 %rd48, %rd48, %rd35;

    // out ptr = out + row*4096*4 + ctaid.x*1024
    ld.param.u64 %rd3, [pOut];
    cvta.to.global.u64 %rd31, %rd3;
    shl.b64 %rd33, %rd42, 14;
    add.u64 %rd37, %rd31, %rd33;
    add.u64 %rd37, %rd37, %rd35;

    mov.u32 %r40, 0;
LEPI_LOOP:
    add.u32 %r41, %r8, %r40;
    tcgen05.ld.sync.aligned.32x32b.x32.b32 {%d0,%d1,%d2,%d3,%d4,%d5,%d6,%d7,%d8,%d9,%d10,%d11,%d12,%d13,%d14,%d15,%d16,%d17,%d18,%d19,%d20,%d21,%d22,%d23,%d24,%d25,%d26,%d27,%d28,%d29,%d30,%d31}, [%r41];
    tcgen05.wait::ld.sync.aligned;

    ld.global.nc.v4.f32 {%w0,%w1,%w2,%w3}, [%rd47+0];
    ld.global.nc.v4.f32 {%x0,%x1,%x2,%x3}, [%rd48+0];
    mul.f32 %w0, %w0, %fA;
    mul.f32 %w1, %w1, %fA;
    mul.f32 %w2, %w2, %fA;
    mul.f32 %w3, %w3, %fA;
    mov.b32 %fv0, %d0;
    mov.b32 %fv1, %d1;
    mov.b32 %fv2, %d2;
    mov.b32 %fv3, %d3;
    fma.rn.f32 %fv0, %fv0, %w0, %x0;
    fma.rn.f32 %fv1, %fv1, %w1, %x1;
    fma.rn.f32 %fv2, %fv2, %w2, %x2;
    fma.rn.f32 %fv3, %fv3, %w3, %x3;
    st.global.v4.f32 [%rd37+0], {%fv0,%fv1,%fv2,%fv3};

    ld.global.nc.v4.f32 {%w0,%w1,%w2,%w3}, [%rd47+16];
    ld.global.nc.v4.f32 {%x0,%x1,%x2,%x3}, [%rd48+16];
    mul.f32 %w0, %w0, %fA;
    mul.f32 %w1, %w1, %fA;
    mul.f32 %w2, %w2, %fA;
    mul.f32 %w3, %w3, %fA;
    mov.b32 %fv0, %d4;
    mov.b32 %fv1, %d5;
    mov.b32 %fv2, %d6;
    mov.b32 %fv3, %d7;
    fma.rn.f32 %fv0, %fv0, %w0, %x0;
    fma.rn.f32 %fv1, %fv1, %w1, %x1;
    fma.rn.f32 %fv2, %fv2, %w2, %x2;
    fma.rn.f32 %fv3, %fv3, %w3, %x3;
    st.global.v4.f32 [%rd37+16], {%fv0,%fv1,%fv2,%fv3};

    ld.global.nc.v4.f32 {%w0,%w1,%w2,%w3}, [%rd47+32];
    ld.global.nc.v4.f32 {%x0,%x1,%x2,%x3}, [%rd48+32];
    mul.f32 %w0, %w0, %fA;
    mul.f32 %w1, %w1, %fA;
    mul.f32 %w2, %w2, %fA;
    mul.f32 %w3, %w3, %fA;
    mov.b32 %fv0, %d8;
    mov.b32 %fv1, %d9;
    mov.b32 %fv2, %d10;
    mov.b32 %fv3, %d11;
    fma.rn.f32 %fv0, %fv0, %w0, %x0;
    fma.rn.f32 %fv1, %fv1, %w1, %x1;
    fma.rn.f32 %fv2, %fv2, %w2, %x2;
    fma.rn.f32 %fv3, %fv3, %w3, %x3;
    st.global.v4.f32 [%rd37+32], {%fv0,%fv1,%fv2,%fv3};

    ld.global.nc.v4.f32 {%w0,%w1,%w2,%w3}, [%rd47+48];
    ld.global.nc.v4.f32 {%x0,%x1,%x2,%x3}, [%rd48+48];
    mul.f32 %w0, %w0, %fA;
    mul.f32 %w1, %w1, %fA;
    mul.f32 %w2, %w2, %fA;
    mul.f32 %w3, %w3, %fA;
    mov.b32 %fv0, %d12;
    mov.b32 %fv1, %d13;
    mov.b32 %fv2, %d14;
    mov.b32 %fv3, %d15;
    fma.rn.f32 %fv0, %fv0, %w0, %x0;
    fma.rn.f32 %fv1, %fv1, %w1, %x1;
    fma.rn.f32 %fv2, %fv2, %w2, %x2;
    fma.rn.f32 %fv3, %fv3, %w3, %x3;
    st.global.v4.f32 [%rd37+48], {%fv0,%fv1,%fv2,%fv3};

    ld.global.nc.v4.f32 {%w0,%w1,%w2,%w3}, [%rd47+64];
    ld.global.nc.v4.f32 {%x0,%x1,%x2,%x3}, [%rd48+64];
    mul.f32 %w0, %w0, %fA;
    mul.f32 %w1, %w1, %fA;
    mul.f32 %w2, %w2, %fA;
    mul.f32 %w3, %w3, %fA;
    mov.b32 %fv0, %d16;
    mov.b32 %fv1, %d17;
    mov.b32 %fv2, %d18;
    mov.b32 %fv3, %d19;
    fma.rn.f32 %fv0, %fv0, %w0, %x0;
    fma.rn.f32 %fv1, %fv1, %w1, %x1;
    fma.rn.f32 %fv2, %fv2, %w2, %x2;
    fma.rn.f32 %fv3, %fv3, %w3, %x3;
    st.global.v4.f32 [%rd37+64], {%fv0,%fv1,%fv2,%fv3};

    ld.global.nc.v4.f32 {%w0,%w1,%w2,%w3}, [%rd47+80];
    ld.global.nc.v4.f32 {%x0,%x1,%x2,%x3}, [%rd48+80];
    mul.f32 %w0, %w0, %fA;
    mul.f32 %w1, %w1, %fA;
    mul.f32 %w2, %w2, %fA;
    mul.f32 %w3, %w3, %fA;
    mov.b32 %fv0, %d20;
    mov.b32 %fv1, %d21;
    mov.b32 %fv2, %d22;
    mov.b32 %fv3, %d23;
    fma.rn.f32 %fv0, %fv0, %w0, %x0;
    fma.rn.f32 %fv1, %fv1, %w1, %x1;
    fma.rn.f32 %fv2, %fv2, %w2, %x2;
    fma.rn.f32 %fv3, %fv3, %w3, %x3;
    st.global.v4.f32 [%rd37+80], {%fv0,%fv1,%fv2,%fv3};

    ld.global.nc.v4.f32 {%w0,%w1,%w2,%w3}, [%rd47+96];
    ld.global.nc.v4.f32 {%x0,%x1,%x2,%x3}, [%rd48+96];
    mul.f32 %w0, %w0, %fA;
    mul.f32 %w1, %w1, %fA;
    mul.f32 %w2, %w2, %fA;
    mul.f32 %w3, %w3, %fA;
    mov.b32 %fv0, %d24;
    mov.b32 %fv1, %d25;
    mov.b32 %fv2, %d26;
    mov.b32 %fv3, %d27;
    fma.rn.f32 %fv0, %fv0, %w0, %x0;
    fma.rn.f32 %fv1, %fv1, %w1, %x1;
    fma.rn.f32 %fv2, %fv2, %w2, %x2;
    fma.rn.f32 %fv3, %fv3, %w3, %x3;
    st.global.v4.f32 [%rd37+96], {%fv0,%fv1,%fv2,%fv3};

    ld.global.nc.v4.f32 {%w0,%w1,%w2,%w3}, [%rd47+112];
    ld.global.nc.v4.f32 {%x0,%x1,%x2,%x3}, [%rd48+112];
    mul.f32 %w0, %w0, %fA;
    mul.f32 %w1, %w1, %fA;
    mul.f32 %w2, %w2, %fA;
    mul.f32 %w3, %w3, %fA;
    mov.b32 %fv0, %d28;
    mov.b32 %fv1, %d29;
    mov.b32 %fv2, %d30;
    mov.b32 %fv3, %d31;
    fma.rn.f32 %fv0, %fv0, %w0, %x0;
    fma.rn.f32 %fv1, %fv1, %w1, %x1;
    fma.rn.f32 %fv2, %fv2, %w2, %x2;
    fma.rn.f32 %fv3, %fv3, %w3, %x3;
    st.global.v4.f32 [%rd37+112], {%fv0,%fv1,%fv2,%fv3};

    add.u64 %rd47, %rd47, 128;
    add.u64 %rd48, %rd48, 128;
    add.u64 %rd37, %rd37, 128;
    add.u32 %r40, %r40, 32;
    setp.lt.u32 %p9, %r40, 256;
    @%p9 bra LEPI_LOOP;

    tcgen05.fence::before_thread_sync;
    bar.sync 0;
    setp.ne.u32 %p1, %r5, 0;
    @%p1 bra LEND;
    mov.u32 %r26, 256;
    tcgen05.dealloc.cta_group::1.sync.aligned.b32 %r8, %r26;
LEND:
    // no CTA may exit while peer multicast may still target its SMEM
    barrier.cluster.arrive.aligned;
    barrier.cluster.wait.aligned;
    ret;
}
)PTX";

#define SMEM_TC 197632  // 1024 + 4 * 49152

// ---------------------------------------------------------------------------
// Driver-JIT with per-stage diagnostics.
// ---------------------------------------------------------------------------
typedef CUresult (*cuLaunchKernelEx_t)(const CUlaunchConfig*, CUfunction,
                                       void**, void**);
namespace {
struct Jit {
    CUfunction fn = nullptr;
    cuLaunchKernelEx_t launchEx = nullptr;
    int  ctor_ran = 0;
    int  stage = 0;
    int  rc = 0;
    char elog[8192];
    char ilog[2048];

    bool try_init() {
        stage = 0; rc = 0; elog[0] = 0; ilog[0] = 0;
        void* h = dlopen("libcuda.so.1", RTLD_LAZY | RTLD_GLOBAL);
        if (!h) h = dlopen("libcuda.so", RTLD_LAZY | RTLD_GLOBAL);
        if (!h) { stage = 1; const char* e = dlerror();
                  if (e) snprintf(elog, sizeof(elog), "%s", e); return false; }
        auto cuInit_p = (CUresult(*)(unsigned))dlsym(h, "cuInit");
        auto devGet_p = (CUresult(*)(CUdevice*, int))dlsym(h, "cuDeviceGet");
        auto ctxRet_p = (CUresult(*)(CUcontext*, CUdevice))dlsym(h, "cuDevicePrimaryCtxRetain");
        auto ctxSet_p = (CUresult(*)(CUcontext))dlsym(h, "cuCtxSetCurrent");
        auto modLoad_p = (CUresult(*)(CUmodule*, const void*, unsigned, CUjit_option*, void**))
                             dlsym(h, "cuModuleLoadDataEx");
        auto getFn_p = (CUresult(*)(CUfunction*, CUmodule, const char*))
                           dlsym(h, "cuModuleGetFunction");
        auto setAttr_p = (CUresult(*)(CUfunction, CUfunction_attribute, int))
                             dlsym(h, "cuFuncSetAttribute");
        auto launchEx_p = (cuLaunchKernelEx_t)dlsym(h, "cuLaunchKernelEx");
        if (!cuInit_p || !devGet_p || !ctxRet_p || !ctxSet_p || !modLoad_p ||
            !getFn_p || !setAttr_p) {
            stage = 2;
            snprintf(elog, sizeof(elog), "dlsym miss");
            return false;
        }
        if (!launchEx_p) { stage = 10; snprintf(elog, sizeof(elog), "no cuLaunchKernelEx"); return false; }
        CUresult r;
        if ((r = cuInit_p(0)) != CUDA_SUCCESS) { stage = 3; rc = (int)r; return false; }
        CUdevice dev;
        if ((r = devGet_p(&dev, 0)) != CUDA_SUCCESS) { stage = 4; rc = (int)r; return false; }
        CUcontext ctx;
        if ((r = ctxRet_p(&ctx, dev)) != CUDA_SUCCESS) { stage = 5; rc = (int)r; return false; }
        if ((r = ctxSet_p(ctx)) != CUDA_SUCCESS) { stage = 6; rc = (int)r; return false; }
        CUjit_option opts[4] = {CU_JIT_ERROR_LOG_BUFFER,
                                CU_JIT_ERROR_LOG_BUFFER_SIZE_BYTES,
                                CU_JIT_INFO_LOG_BUFFER,
                                CU_JIT_INFO_LOG_BUFFER_SIZE_BYTES};
        void* vals[4] = {elog, (void*)(size_t)sizeof(elog),
                         ilog, (void*)(size_t)sizeof(ilog)};
        CUmodule mod;
        if ((r = modLoad_p(&mod, GEMM_PTX, 4, opts, vals)) != CUDA_SUCCESS) {
            stage = 7; rc = (int)r; return false;
        }
        CUfunction f;
        if ((r = getFn_p(&f, mod, "gemm_tc")) != CUDA_SUCCESS) {
            stage = 8; rc = (int)r; return false;
        }
        if ((r = setAttr_p(f, CU_FUNC_ATTRIBUTE_MAX_DYNAMIC_SHARED_SIZE_BYTES, SMEM_TC))
            != CUDA_SUCCESS) { stage = 9; rc = (int)r; return false; }
        fn = f;
        launchEx = launchEx_p;
        return true;
    }
    Jit() { ctor_ran = 1; try_init(); }
};
Jit g_jit;
}  // namespace

// ---------------------------------------------------------------------------
// Kernel 0: input-format detection (parallel).
// ---------------------------------------------------------------------------
__global__ void detect_kernel(const int* __restrict__ w,
                              const float* __restrict__ c2) {
    __shared__ int s_w_in_range;
    __shared__ int s_c2_scalelike;
    const int tid = threadIdx.x;
    if (tid == 0) { s_w_in_range = 1; s_c2_scalelike = 1; }
    __syncthreads();

    int bad_w = 0;
#pragma unroll
    for (int i = 0; i < 8; i++) {
        int v = w[tid + i * 256];
        if (v < -128 || v > 127) bad_w = 1;
    }
    float cv = c2[tid];
    int bad_c2 = !(cv > 0.0f && cv < 0.02f);

    if (__syncthreads_or(bad_w)) { if (tid == 0) s_w_in_range = 0; }
    if (__syncthreads_or(bad_c2)) { if (tid == 0) s_c2_scalelike = 0; }
    __syncthreads();
    if (tid == 0) {
        g_w_is_i32 = s_w_in_range;
        g_sb_swap = s_c2_scalelike ? 0 : 1;
    }
}

// ---------------------------------------------------------------------------
// Kernel 1: per-row dynamic quantization -> bf16, tiled+swizzled g_xb.
// ---------------------------------------------------------------------------
__global__ void quantize_rows_kernel(const float* __restrict__ x) {
    const int row = blockIdx.x;
    const int tid = threadIdx.x;

    const float4* xr = reinterpret_cast<const float4*>(x) + (size_t)row * (KDIM / 4);
    float4 v[4];
    float amax = 0.0f;
#pragma unroll
    for (int i = 0; i < 4; i++) {
        v[i] = xr[tid + i * 256];
        amax = fmaxf(amax, fmaxf(fmaxf(fabsf(v[i].x), fabsf(v[i].y)),
                                 fmaxf(fabsf(v[i].z), fabsf(v[i].w))));
    }
#pragma unroll
    for (int o = 16; o; o >>= 1)
        amax = fmaxf(amax, __shfl_xor_sync(0xFFFFFFFFu, amax, o));

    __shared__ float sm_[8];
    __shared__ float s_scale;
    if ((tid & 31) == 0) sm_[tid >> 5] = amax;
    __syncthreads();
    if (tid == 0) {
        float m = sm_[0];
#pragma unroll
        for (int i = 1; i < 8; i++) m = fmaxf(m, sm_[i]);
        float s = fmaxf(m / 127.0f, 1e-8f);
        g_ascale[row] = s;
        s_scale = s;
    }
    __syncthreads();

    const float inv = 1.0f / s_scale;
    const int mt = row >> 7, r = row & 127;
    const size_t mbase = ((size_t)mt * 64) << 14;
#pragma unroll
    for (int i = 0; i < 4; i++) {
        int q0 = max(-128, min(127, __float2int_rn(v[i].x * inv)));
        int q1 = max(-128, min(127, __float2int_rn(v[i].y * inv)));
        int q2 = max(-128, min(127, __float2int_rn(v[i].z * inv)));
        int q3 = max(-128, min(127, __float2int_rn(v[i].w * inv)));
        __nv_bfloat162 p0 = __floats2bfloat162_rn((float)q0, (float)q1);
        __nv_bfloat162 p1 = __floats2bfloat162_rn((float)q2, (float)q3);
        uint2 packed;
        packed.x = *reinterpret_cast<unsigned int*>(&p0);
        packed.y = *reinterpret_cast<unsigned int*>(&p1);
        int k = (tid + i * 256) * 4;
        int kt = k >> 6, c = k & 63;
        size_t addr = mbase + ((size_t)kt << 14) + SWZ(r * 128 + c * 2);
        *reinterpret_cast<uint2*>(g_xb + addr) = packed;
    }
}

// ---------------------------------------------------------------------------
// Kernel 2: transpose weight [K, N] -> bf16 tiled+swizzled g_wb [N, K] tiles.
// ---------------------------------------------------------------------------
__global__ void transpose_w_kernel(const void* __restrict__ wraw) {
    __shared__ uint8_t t[128][36];
    const int tid = threadIdx.x;
    const int n0 = blockIdx.x * 128;
    const int k0 = blockIdx.y * 32;

    if (g_w_is_i32) {
        const int* w = (const int*)wraw;
#pragma unroll
        for (int it = 0; it < 4; it++) {
            int i = tid + it * 256;
            int k = i >> 5, n4 = i & 31;
            int4 wv = *reinterpret_cast<const int4*>(
                w + (size_t)(k0 + k) * NDIM + n0 + n4 * 4);
            t[n4 * 4 + 0][k] = (uint8_t)wv.x;
            t[n4 * 4 + 1][k] = (uint8_t)wv.y;
            t[n4 * 4 + 2][k] = (uint8_t)wv.z;
            t[n4 * 4 + 3][k] = (uint8_t)wv.w;
        }
    } else {
        const int8_t* w = (const int8_t*)wraw;
#pragma unroll
        for (int it = 0; it < 4; it++) {
            int i = tid + it * 256;
            int k = i >> 5, n4 = i & 31;
            unsigned int wv = *reinterpret_cast<const unsigned int*>(
                w + (size_t)(k0 + k) * NDIM + n0 + n4 * 4);
            t[n4 * 4 + 0][k] = (uint8_t)(wv & 0xFF);
            t[n4 * 4 + 1][k] = (uint8_t)((wv >> 8) & 0xFF);
            t[n4 * 4 + 2][k] = (uint8_t)((wv >> 16) & 0xFF);
            t[n4 * 4 + 3][k] = (uint8_t)((wv >> 24) & 0xFF);
        }
    }
    __syncthreads();

    const int ntile = n0 >> 7;
#pragma unroll
    for (int it = 0; it < 4; it++) {
        int i = tid + it * 256;
        int n = i >> 3, kw = i & 7;
        float f0 = (float)(int8_t)t[n][kw * 4 + 0];
        float f1 = (float)(int8_t)t[n][kw * 4 + 1];
        float f2 = (float)(int8_t)t[n][kw * 4 + 2];
        float f3 = (float)(int8_t)t[n][kw * 4 + 3];
        __nv_bfloat162 p0 = __floats2bfloat162_rn(f0, f1);
        __nv_bfloat162 p1 = __floats2bfloat162_rn(f2, f3);
        uint2 packed;
        packed.x = *reinterpret_cast<unsigned int*>(&p0);
        packed.y = *reinterpret_cast<unsigned int*>(&p1);
        int kglob = k0 + kw * 4;
        int kt = kglob >> 6, c = kglob & 63;
        size_t addr = (((size_t)ntile * 64 + kt) << 14) + SWZ(n * 128 + c * 2);
        *reinterpret_cast<uint2*>(g_wb + addr) = packed;
    }
}

// ---------------------------------------------------------------------------
extern "C" void kernel_launch(void* const* d_in, const int* in_sizes, int n_in,
                              void* d_out, int out_size) {
    int idx_x = -1, idx_w = -1, idx_a = -1, idx_b = -1;
    for (int i = 0; i < n_in; i++) {
        long s = in_sizes[i];
        if (s == (long)MDIM * KDIM) idx_x = i;
        else if (s == (long)KDIM * NDIM) idx_w = i;
        else if (idx_a < 0) idx_a = i;
        else idx_b = i;
    }
    if (idx_x < 0 || idx_w < 0 || idx_a < 0 || idx_b < 0) {
        idx_x = 0; idx_w = 1; idx_a = 2; idx_b = 3;
    }

    const float* x  = (const float*)d_in[idx_x];
    const void*  wq = d_in[idx_w];
    const float* c2 = (const float*)d_in[idx_a];
    const float* c3 = (const float*)d_in[idx_b];
    float* out = (float*)d_out;

    static int static_init_ok = (g_jit.fn != nullptr) ? 1 : 0;
    if (!g_jit.fn) g_jit.try_init();

    if (!g_jit.fn) {
        fprintf(stderr,
                "JIT DIAG: ctor_ran=%d static_ok=%d stage=%d rc=%d\n"
                "--- error log ---\n%s\n--- info log ---\n%s\n",
                g_jit.ctor_ran, static_init_ok, g_jit.stage, g_jit.rc,
                g_jit.elog, g_jit.ilog);
        fflush(stderr);
        _Exit(3);
    }

    detect_kernel<<<1, 256>>>((const int*)wq, c2);
    quantize_rows_kernel<<<MDIM, 256>>>(x);
    transpose_w_kernel<<<dim3(NDIM / 128, KDIM / 32), 256>>>(wq);

    void *pa = nullptr, *pb = nullptr, *pasc = nullptr, *psb = nullptr;
    cudaGetSymbolAddress(&pa, g_xb);
    cudaGetSymbolAddress(&pb, g_wb);
    cudaGetSymbolAddress(&pasc, g_ascale);
    cudaGetSymbolAddress(&psb, g_sb_swap);
    void* pc2 = (void*)c2;
    void* pc3 = (void*)c3;
    void* pout = (void*)out;
    void* args[7] = {&pa, &pb, &pasc, &pc2, &pc3, &psb, &pout};

    // Cluster (1,2) launch on the per-thread default stream (legacy stream
    // would invalidate graph capture).
    CUlaunchAttribute attrs[1];
    memset(attrs, 0, sizeof(attrs));
    attrs[0].id = CU_LAUNCH_ATTRIBUTE_CLUSTER_DIMENSION;
    attrs[0].value.clusterDim.x = 1;
    attrs[0].value.clusterDim.y = 2;
    attrs[0].value.clusterDim.z = 1;
    CUlaunchConfig cfg;
    memset(&cfg, 0, sizeof(cfg));
    cfg.gridDimX = NDIM / 256;
    cfg.gridDimY = MDIM / 128;
    cfg.gridDimZ = 1;
    cfg.blockDimX = 128;
    cfg.blockDimY = 1;
    cfg.blockDimZ = 1;
    cfg.sharedMemBytes = SMEM_TC;
    cfg.hStream = (CUstream)0x2;  // CU_STREAM_PER_THREAD
    cfg.attrs = attrs;
    cfg.numAttrs = 1;
    CUresult lr = g_jit.launchEx(&cfg, g_jit.fn, args, nullptr);
    if (lr != CUDA_SUCCESS) {
        fprintf(stderr, "LAUNCH DIAG: cuLaunchKernelEx rc=%d\n", (int)lr);
        fflush(stderr);
        _Exit(4);
    }
}

// round 17
// speedup vs baseline: 1.2895x; 1.2895x over previous
#include <cuda_runtime.h>
#include <cuda_bf16.h>
#include <cuda.h>
#include <dlfcn.h>
#include <cstdint>
#include <cstdio>
#include <cstdlib>
#include <cstring>

// Problem constants
#define MDIM 8192
#define KDIM 4096
#define NDIM 4096

// SW128 swizzle (Swizzle<3,4,3>) on byte offsets
#define SWZ(o) ((o) ^ (((o) >> 3) & 0x70))

// Scratch (static __device__; no allocation anywhere).
// g_xb: quantized activations as bf16, 128(M)x64(K) tiles of 16KB, SW128
//   pre-swizzled. Tile (mt, kt) at ((mt*64 + kt) << 14).  64 MB.
// g_wb: weights (transposed to [N,K]) as bf16, same tiling. 32 MB.
__device__ __align__(1024) uint8_t g_xb[(size_t)MDIM * KDIM * 2];
__device__ __align__(1024) uint8_t g_wb[(size_t)NDIM * KDIM * 2];
__device__ float g_ascale[MDIM];
__device__ int   g_w_is_i32;
__device__ int   g_sb_swap;

// ===========================================================================
// Hand-written PTX (sm_103a, ISA 8.8) loaded via driver JIT.
// PERSISTENT tcgen05 bf16 GEMM. 148 CTAs x 192 threads:
//   warps 0-3 (tid<128)  = epilogue workers (TMEM drain + fused dequant)
//   tid 128              = MMA issuer
//   tid 160              = TMA producer
// TMEM: 512 cols = TWO 256-col accumulator buffers. Tile t -> buffer t&1.
// While MMA fills buffer B for tile i+1, epilogue drains buffer A of tile i
// -> epilogue hidden behind the mainloop (R16 showed it was serial dead time).
// Tiles: 1024 = 64(mt) x 16(nt); CTA c handles t = c, c+148, ...
// Per tile: 64 K-chunks (4 x K=16 MMA each), 4-stage SMEM pipeline.
// Sync: done[buf] (issuer commit, cnt1) -> epilogue; epi[buf] (cnt128) ->
// issuer may overwrite buffer (waits tile i-2's drain).
// ===========================================================================
static const char* GEMM_PTX = R"PTX(
.version 8.8
.target sm_103a
.address_size 64

.extern .shared .align 1024 .b8 sm[];

.visible .entry gemm_tc(
    .param .u64 pA,
    .param .u64 pB,
    .param .u64 pASC,
    .param .u64 pC2,
    .param .u64 pC3,
    .param .u64 pSB,
    .param .u64 pOut
)
.reqntid 192, 1, 1
{
    .reg .pred %p<16>;
    .reg .b32 %r<64>;
    .reg .b64 %rd<64>;
    .reg .b32 %d<32>;
    .reg .f32 %w<4>;
    .reg .f32 %x<4>;
    .reg .f32 %fv<4>;
    .reg .f32 %fA;

    mov.u32 %r1, %tid.x;
    mov.u32 %r2, %ctaid.x;
    mov.u32 %r4, sm;
    shr.u32 %r5, %r1, 5;
    and.b32 %r6, %r1, 31;
    mov.u32 %r50, 0;

    // ---- TMEM alloc (warp 0): 512 cols = 2 buffers of 256 ----
    setp.ne.u32 %p1, %r5, 0;
    @%p1 bra LNOALLOC;
    mov.u32 %r26, 512;
    tcgen05.alloc.cta_group::1.sync.aligned.shared::cta.b32 [%r4], %r26;
    tcgen05.relinquish_alloc_permit.cta_group::1.sync.aligned;
LNOALLOC:

    // ---- barrier init (tid 0) ----
    // full[s]=16+16s cnt1, empty[s]=24+16s cnt1,
    // done[b]=96+8b cnt1, epi[b]=112+8b cnt128
    setp.ne.u32 %p2, %r1, 0;
    @%p2 bra LINIT_DONE;
    add.u32 %r7, %r4, 16;
    mbarrier.init.shared.b64 [%r7], 1;
    add.u32 %r7, %r4, 24;
    mbarrier.init.shared.b64 [%r7], 1;
    add.u32 %r7, %r4, 32;
    mbarrier.init.shared.b64 [%r7], 1;
    add.u32 %r7, %r4, 40;
    mbarrier.init.shared.b64 [%r7], 1;
    add.u32 %r7, %r4, 48;
    mbarrier.init.shared.b64 [%r7], 1;
    add.u32 %r7, %r4, 56;
    mbarrier.init.shared.b64 [%r7], 1;
    add.u32 %r7, %r4, 64;
    mbarrier.init.shared.b64 [%r7], 1;
    add.u32 %r7, %r4, 72;
    mbarrier.init.shared.b64 [%r7], 1;
    add.u32 %r7, %r4, 96;
    mbarrier.init.shared.b64 [%r7], 1;
    add.u32 %r7, %r4, 104;
    mbarrier.init.shared.b64 [%r7], 1;
    add.u32 %r7, %r4, 112;
    mbarrier.init.shared.b64 [%r7], 128;
    add.u32 %r7, %r4, 120;
    mbarrier.init.shared.b64 [%r7], 128;
LINIT_DONE:
    bar.sync 0;
    ld.shared.b32 %r8, [%r4];

    setp.lt.u32 %p3, %r1, 128;
    @%p3 bra LEPI_WORK;
    setp.eq.u32 %p3, %r1, 128;
    @%p3 bra LISSUER;
    setp.eq.u32 %p3, %r1, 160;
    @%p3 bra LPRODUCER;
    bra LFINAL;

    // ================= MMA issuer (tid 128) =================
LISSUER:
    mov.u32 %r10, 0;          // global chunk counter
    mov.u32 %r11, 0;          // pipeline phase
    mov.u32 %r42, 0;          // local tile index rT
    mov.u32 %r43, %r2;        // global tile id tg
    mov.u64 %rd6, 0x4000404000010000;   // SW128 K-major desc base
    mov.u32 %r20, 0x08400490;           // idesc: F32, BF16xBF16, M=128, N=256
    setp.eq.u32 %p6, %r50, 0;           // always-true (accumulate)
LT_ISS:
    setp.ge.u32 %p9, %r43, 1024;
    @%p9 bra LFINAL;
    and.b32 %r44, %r42, 1;              // buf
    setp.lt.u32 %p7, %r42, 2;
    @%p7 bra LISS_NOEPI;
    // wait epilogue of tile rT-2 (same buffer): parity ((rT>>1)&1)^1
    shr.u32 %r45, %r42, 1;
    xor.b32 %r45, %r45, 1;
    and.b32 %r45, %r45, 1;
    shl.b32 %r46, %r44, 3;
    add.u32 %r46, %r46, 112;
    add.u32 %r46, %r46, %r4;            // epi[buf]
LISS_EPIWAIT:
    mbarrier.try_wait.parity.shared.b64 %p4, [%r46], %r45;
    @!%p4 bra LISS_EPIWAIT;
    tcgen05.fence::after_thread_sync;
LISS_NOEPI:
    shl.b32 %r47, %r44, 8;
    add.u32 %r48, %r8, %r47;            // d_tmem = base + buf*256
    mov.u32 %r49, 0;                    // chunk-in-tile c
LC_ISS:
    and.b32 %r12, %r10, 3;
    shl.b32 %r13, %r12, 4;
    add.u32 %r14, %r4, 16;
    add.u32 %r14, %r14, %r13;           // full[s]
LISS_WAIT:
    mbarrier.try_wait.parity.shared.b64 %p4, [%r14], %r11;
    @!%p4 bra LISS_WAIT;
    mul.lo.u32 %r15, %r12, 49152;
    add.u32 %r16, %r4, 1024;
    add.u32 %r16, %r16, %r15;           // stage base (A)
    shr.u32 %r17, %r16, 4;
    and.b32 %r17, %r17, 16383;
    cvt.u64.u32 %rd7, %r17;
    or.b64 %rd8, %rd6, %rd7;            // A desc
    add.u32 %r18, %r16, 16384;
    shr.u32 %r19, %r18, 4;
    and.b32 %r19, %r19, 16383;
    cvt.u64.u32 %rd9, %r19;
    or.b64 %rd10, %rd6, %rd9;           // B desc
    setp.ne.u32 %p5, %r49, 0;           // accumulate except first chunk of tile
    tcgen05.mma.cta_group::1.kind::f16 [%r48], %rd8, %rd10, %r20, {%r50,%r50,%r50,%r50}, %p5;
    add.u64 %rd11, %rd8, 2;
    add.u64 %rd12, %rd10, 2;
    tcgen05.mma.cta_group::1.kind::f16 [%r48], %rd11, %rd12, %r20, {%r50,%r50,%r50,%r50}, %p6;
    add.u64 %rd11, %rd8, 4;
    add.u64 %rd12, %rd10, 4;
    tcgen05.mma.cta_group::1.kind::f16 [%r48], %rd11, %rd12, %r20, {%r50,%r50,%r50,%r50}, %p6;
    add.u64 %rd11, %rd8, 6;
    add.u64 %rd12, %rd10, 6;
    tcgen05.mma.cta_group::1.kind::f16 [%r48], %rd11, %rd12, %r20, {%r50,%r50,%r50,%r50}, %p6;
    add.u32 %r21, %r14, 8;              // empty[s]
    tcgen05.commit.cta_group::1.mbarrier::arrive::one.shared::cluster.b64 [%r21];
    setp.eq.u32 %p8, %r12, 3;
    xor.b32 %r24, %r11, 1;
    selp.b32 %r11, %r24, %r11, %p8;
    add.u32 %r10, %r10, 1;
    add.u32 %r49, %r49, 1;
    setp.lt.u32 %p9, %r49, 64;
    @%p9 bra LC_ISS;
    // tile complete -> done[buf]
    shl.b32 %r46, %r44, 3;
    add.u32 %r46, %r46, 96;
    add.u32 %r46, %r46, %r4;
    tcgen05.commit.cta_group::1.mbarrier::arrive::one.shared::cluster.b64 [%r46];
    add.u32 %r42, %r42, 1;
    add.u32 %r43, %r43, 148;
    bra LT_ISS;

    // ================= producer (tid 160) =================
LPRODUCER:
    ld.param.u64 %rd1, [pA];
    ld.param.u64 %rd2, [pB];
    mov.u32 %r10, 0;
    mov.u32 %r11, 1;
    mov.u32 %r43, %r2;
    mov.u32 %r25, 16384;
    mov.u32 %r27, 49152;
LT_PROD:
    setp.ge.u32 %p9, %r43, 1024;
    @%p9 bra LFINAL;
    shr.u32 %r52, %r43, 4;              // mt
    and.b32 %r53, %r43, 15;             // nt
    cvt.u64.u32 %rd20, %r52;
    shl.b64 %rd21, %rd20, 20;           // mt * 64 tiles * 16KB
    add.u64 %rd22, %rd1, %rd21;
    cvt.u64.u32 %rd23, %r53;
    shl.b64 %rd24, %rd23, 21;           // nt * 2 * 64 * 16KB
    add.u64 %rd25, %rd2, %rd24;
    mov.u32 %r49, 0;
LC_PROD:
    and.b32 %r12, %r10, 3;
    shl.b32 %r13, %r12, 4;
    add.u32 %r14, %r4, 24;
    add.u32 %r14, %r14, %r13;           // empty[s]
LPROD_WAIT:
    mbarrier.try_wait.parity.shared.b64 %p4, [%r14], %r11;
    @!%p4 bra LPROD_WAIT;
    sub.u32 %r15, %r14, 8;              // full[s]
    mbarrier.arrive.expect_tx.shared.b64 %rd40, [%r15], %r27;
    mul.lo.u32 %r16, %r12, 49152;
    add.u32 %r17, %r4, 1024;
    add.u32 %r17, %r17, %r16;
    cvt.u64.u32 %rd26, %r49;
    shl.b64 %rd27, %rd26, 14;           // kt * 16KB
    add.u64 %rd28, %rd22, %rd27;
    cp.async.bulk.shared::cta.global.mbarrier::complete_tx::bytes [%r17], [%rd28], %r25, [%r15];
    add.u64 %rd29, %rd25, %rd27;
    add.u32 %r18, %r17, 16384;
    cp.async.bulk.shared::cta.global.mbarrier::complete_tx::bytes [%r18], [%rd29], %r25, [%r15];
    add.u64 %rd30, %rd29, 1048576;
    add.u32 %r19, %r17, 32768;
    cp.async.bulk.shared::cta.global.mbarrier::complete_tx::bytes [%r19], [%rd30], %r25, [%r15];
    setp.eq.u32 %p8, %r12, 3;
    xor.b32 %r24, %r11, 1;
    selp.b32 %r11, %r24, %r11, %p8;
    add.u32 %r10, %r10, 1;
    add.u32 %r49, %r49, 1;
    setp.lt.u32 %p9, %r49, 64;
    @%p9 bra LC_PROD;
    add.u32 %r43, %r43, 148;
    bra LT_PROD;

    // ================= epilogue workers (tid < 128) =================
LEPI_WORK:
    ld.param.u64 %rd45, [pC2];
    ld.param.u64 %rd46, [pC3];
    ld.param.u64 %rd44, [pSB];
    cvta.to.global.u64 %rd44, %rd44;
    ld.global.u32 %r34, [%rd44];
    setp.ne.u32 %p10, %r34, 0;
    selp.b64 %rd57, %rd46, %rd45, %p10;   // wscale
    selp.b64 %rd58, %rd45, %rd46, %p10;   // bias
    cvta.to.global.u64 %rd57, %rd57;
    cvta.to.global.u64 %rd58, %rd58;
    ld.param.u64 %rd3, [pOut];
    cvta.to.global.u64 %rd31, %rd3;
    ld.param.u64 %rd41, [pASC];
    cvta.to.global.u64 %rd59, %rd41;
    mov.u32 %r42, 0;
    mov.u32 %r43, %r2;
LT_EPI:
    setp.ge.u32 %p9, %r43, 1024;
    @%p9 bra LFINAL;
    and.b32 %r44, %r42, 1;              // buf
    shr.u32 %r45, %r42, 1;
    and.b32 %r45, %r45, 1;              // done parity
    shl.b32 %r46, %r44, 3;
    add.u32 %r46, %r46, 96;
    add.u32 %r46, %r46, %r4;            // done[buf]
LEPI_DWAIT:
    mbarrier.try_wait.parity.shared.b64 %p4, [%r46], %r45;
    @!%p4 bra LEPI_DWAIT;
    tcgen05.fence::after_thread_sync;
    shr.u32 %r52, %r43, 4;              // mt
    and.b32 %r53, %r43, 15;             // nt
    shl.b32 %r32, %r52, 7;
    shl.b32 %r33, %r5, 5;
    add.u32 %r32, %r32, %r33;
    add.u32 %r32, %r32, %r6;            // global row
    cvt.u64.u32 %rd42, %r32;
    shl.b64 %rd43, %rd42, 2;
    add.u64 %rd60, %rd59, %rd43;
    ld.global.nc.f32 %fA, [%rd60];
    cvt.u64.u32 %rd34, %r53;
    shl.b64 %rd35, %rd34, 10;           // nt * 256 cols * 4B
    add.u64 %rd47, %rd57, %rd35;
    add.u64 %rd48, %rd58, %rd35;
    shl.b64 %rd33, %rd42, 14;           // row * 4096 * 4B
    add.u64 %rd37, %rd31, %rd33;
    add.u64 %rd37, %rd37, %rd35;
    shl.b32 %r47, %r44, 8;
    add.u32 %r48, %r8, %r47;            // tmem drain base
    mov.u32 %r40, 0;
LEPI_LOOP:
    add.u32 %r41, %r48, %r40;
    tcgen05.ld.sync.aligned.32x32b.x32.b32 {%d0,%d1,%d2,%d3,%d4,%d5,%d6,%d7,%d8,%d9,%d10,%d11,%d12,%d13,%d14,%d15,%d16,%d17,%d18,%d19,%d20,%d21,%d22,%d23,%d24,%d25,%d26,%d27,%d28,%d29,%d30,%d31}, [%r41];
    tcgen05.wait::ld.sync.aligned;

    ld.global.nc.v4.f32 {%w0,%w1,%w2,%w3}, [%rd47+0];
    ld.global.nc.v4.f32 {%x0,%x1,%x2,%x3}, [%rd48+0];
    mul.f32 %w0, %w0, %fA;
    mul.f32 %w1, %w1, %fA;
    mul.f32 %w2, %w2, %fA;
    mul.f32 %w3, %w3, %fA;
    mov.b32 %fv0, %d0;
    mov.b32 %fv1, %d1;
    mov.b32 %fv2, %d2;
    mov.b32 %fv3, %d3;
    fma.rn.f32 %fv0, %fv0, %w0, %x0;
    fma.rn.f32 %fv1, %fv1, %w1, %x1;
    fma.rn.f32 %fv2, %fv2, %w2, %x2;
    fma.rn.f32 %fv3, %fv3, %w3, %x3;
    st.global.v4.f32 [%rd37+0], {%fv0,%fv1,%fv2,%fv3};

    ld.global.nc.v4.f32 {%w0,%w1,%w2,%w3}, [%rd47+16];
    ld.global.nc.v4.f32 {%x0,%x1,%x2,%x3}, [%rd48+16];
    mul.f32 %w0, %w0, %fA;
    mul.f32 %w1, %w1, %fA;
    mul.f32 %w2, %w2, %fA;
    mul.f32 %w3, %w3, %fA;
    mov.b32 %fv0, %d4;
    mov.b32 %fv1, %d5;
    mov.b32 %fv2, %d6;
    mov.b32 %fv3, %d7;
    fma.rn.f32 %fv0, %fv0, %w0, %x0;
    fma.rn.f32 %fv1, %fv1, %w1, %x1;
    fma.rn.f32 %fv2, %fv2, %w2, %x2;
    fma.rn.f32 %fv3, %fv3, %w3, %x3;
    st.global.v4.f32 [%rd37+16], {%fv0,%fv1,%fv2,%fv3};

    ld.global.nc.v4.f32 {%w0,%w1,%w2,%w3}, [%rd47+32];
    ld.global.nc.v4.f32 {%x0,%x1,%x2,%x3}, [%rd48+32];
    mul.f32 %w0, %w0, %fA;
    mul.f32 %w1, %w1, %fA;
    mul.f32 %w2, %w2, %fA;
    mul.f32 %w3, %w3, %fA;
    mov.b32 %fv0, %d8;
    mov.b32 %fv1, %d9;
    mov.b32 %fv2, %d10;
    mov.b32 %fv3, %d11;
    fma.rn.f32 %fv0, %fv0, %w0, %x0;
    fma.rn.f32 %fv1, %fv1, %w1, %x1;
    fma.rn.f32 %fv2, %fv2, %w2, %x2;
    fma.rn.f32 %fv3, %fv3, %w3, %x3;
    st.global.v4.f32 [%rd37+32], {%fv0,%fv1,%fv2,%fv3};

    ld.global.nc.v4.f32 {%w0,%w1,%w2,%w3}, [%rd47+48];
    ld.global.nc.v4.f32 {%x0,%x1,%x2,%x3}, [%rd48+48];
    mul.f32 %w0, %w0, %fA;
    mul.f32 %w1, %w1, %fA;
    mul.f32 %w2, %w2, %fA;
    mul.f32 %w3, %w3, %fA;
    mov.b32 %fv0, %d12;
    mov.b32 %fv1, %d13;
    mov.b32 %fv2, %d14;
    mov.b32 %fv3, %d15;
    fma.rn.f32 %fv0, %fv0, %w0, %x0;
    fma.rn.f32 %fv1, %fv1, %w1, %x1;
    fma.rn.f32 %fv2, %fv2, %w2, %x2;
    fma.rn.f32 %fv3, %fv3, %w3, %x3;
    st.global.v4.f32 [%rd37+48], {%fv0,%fv1,%fv2,%fv3};

    ld.global.nc.v4.f32 {%w0,%w1,%w2,%w3}, [%rd47+64];
    ld.global.nc.v4.f32 {%x0,%x1,%x2,%x3}, [%rd48+64];
    mul.f32 %w0, %w0, %fA;
    mul.f32 %w1, %w1, %fA;
    mul.f32 %w2, %w2, %fA;
    mul.f32 %w3, %w3, %fA;
    mov.b32 %fv0, %d16;
    mov.b32 %fv1, %d17;
    mov.b32 %fv2, %d18;
    mov.b32 %fv3, %d19;
    fma.rn.f32 %fv0, %fv0, %w0, %x0;
    fma.rn.f32 %fv1, %fv1, %w1, %x1;
    fma.rn.f32 %fv2, %fv2, %w2, %x2;
    fma.rn.f32 %fv3, %fv3, %w3, %x3;
    st.global.v4.f32 [%rd37+64], {%fv0,%fv1,%fv2,%fv3};

    ld.global.nc.v4.f32 {%w0,%w1,%w2,%w3}, [%rd47+80];
    ld.global.nc.v4.f32 {%x0,%x1,%x2,%x3}, [%rd48+80];
    mul.f32 %w0, %w0, %fA;
    mul.f32 %w1, %w1, %fA;
    mul.f32 %w2, %w2, %fA;
    mul.f32 %w3, %w3, %fA;
    mov.b32 %fv0, %d20;
    mov.b32 %fv1, %d21;
    mov.b32 %fv2, %d22;
    mov.b32 %fv3, %d23;
    fma.rn.f32 %fv0, %fv0, %w0, %x0;
    fma.rn.f32 %fv1, %fv1, %w1, %x1;
    fma.rn.f32 %fv2, %fv2, %w2, %x2;
    fma.rn.f32 %fv3, %fv3, %w3, %x3;
    st.global.v4.f32 [%rd37+80], {%fv0,%fv1,%fv2,%fv3};

    ld.global.nc.v4.f32 {%w0,%w1,%w2,%w3}, [%rd47+96];
    ld.global.nc.v4.f32 {%x0,%x1,%x2,%x3}, [%rd48+96];
    mul.f32 %w0, %w0, %fA;
    mul.f32 %w1, %w1, %fA;
    mul.f32 %w2, %w2, %fA;
    mul.f32 %w3, %w3, %fA;
    mov.b32 %fv0, %d24;
    mov.b32 %fv1, %d25;
    mov.b32 %fv2, %d26;
    mov.b32 %fv3, %d27;
    fma.rn.f32 %fv0, %fv0, %w0, %x0;
    fma.rn.f32 %fv1, %fv1, %w1, %x1;
    fma.rn.f32 %fv2, %fv2, %w2, %x2;
    fma.rn.f32 %fv3, %fv3, %w3, %x3;
    st.global.v4.f32 [%rd37+96], {%fv0,%fv1,%fv2,%fv3};

    ld.global.nc.v4.f32 {%w0,%w1,%w2,%w3}, [%rd47+112];
    ld.global.nc.v4.f32 {%x0,%x1,%x2,%x3}, [%rd48+112];
    mul.f32 %w0, %w0, %fA;
    mul.f32 %w1, %w1, %fA;
    mul.f32 %w2, %w2, %fA;
    mul.f32 %w3, %w3, %fA;
    mov.b32 %fv0, %d28;
    mov.b32 %fv1, %d29;
    mov.b32 %fv2, %d30;
    mov.b32 %fv3, %d31;
    fma.rn.f32 %fv0, %fv0, %w0, %x0;
    fma.rn.f32 %fv1, %fv1, %w1, %x1;
    fma.rn.f32 %fv2, %fv2, %w2, %x2;
    fma.rn.f32 %fv3, %fv3, %w3, %x3;
    st.global.v4.f32 [%rd37+112], {%fv0,%fv1,%fv2,%fv3};

    add.u64 %rd47, %rd47, 128;
    add.u64 %rd48, %rd48, 128;
    add.u64 %rd37, %rd37, 128;
    add.u32 %r40, %r40, 32;
    setp.lt.u32 %p9, %r40, 256;
    @%p9 bra LEPI_LOOP;

    tcgen05.fence::before_thread_sync;
    shl.b32 %r46, %r44, 3;
    add.u32 %r46, %r46, 112;
    add.u32 %r46, %r46, %r4;            // epi[buf]
    mbarrier.arrive.shared.b64 %rd40, [%r46];
    add.u32 %r42, %r42, 1;
    add.u32 %r43, %r43, 148;
    bra LT_EPI;

LFINAL:
    bar.sync 0;
    setp.ne.u32 %p1, %r5, 0;
    @%p1 bra LEND;
    mov.u32 %r26, 512;
    tcgen05.dealloc.cta_group::1.sync.aligned.b32 %r8, %r26;
LEND:
    ret;
}
)PTX";

#define SMEM_TC 197632  // 1024 + 4 * 49152

// ---------------------------------------------------------------------------
// Driver-JIT with per-stage diagnostics.
// ---------------------------------------------------------------------------
typedef CUresult (*cuLaunchKernelEx_t)(const CUlaunchConfig*, CUfunction,
                                       void**, void**);
namespace {
struct Jit {
    CUfunction fn = nullptr;
    cuLaunchKernelEx_t launchEx = nullptr;
    int  ctor_ran = 0;
    int  stage = 0;
    int  rc = 0;
    char elog[8192];
    char ilog[2048];

    bool try_init() {
        stage = 0; rc = 0; elog[0] = 0; ilog[0] = 0;
        void* h = dlopen("libcuda.so.1", RTLD_LAZY | RTLD_GLOBAL);
        if (!h) h = dlopen("libcuda.so", RTLD_LAZY | RTLD_GLOBAL);
        if (!h) { stage = 1; const char* e = dlerror();
                  if (e) snprintf(elog, sizeof(elog), "%s", e); return false; }
        auto cuInit_p = (CUresult(*)(unsigned))dlsym(h, "cuInit");
        auto devGet_p = (CUresult(*)(CUdevice*, int))dlsym(h, "cuDeviceGet");
        auto ctxRet_p = (CUresult(*)(CUcontext*, CUdevice))dlsym(h, "cuDevicePrimaryCtxRetain");
        auto ctxSet_p = (CUresult(*)(CUcontext))dlsym(h, "cuCtxSetCurrent");
        auto modLoad_p = (CUresult(*)(CUmodule*, const void*, unsigned, CUjit_option*, void**))
                             dlsym(h, "cuModuleLoadDataEx");
        auto getFn_p = (CUresult(*)(CUfunction*, CUmodule, const char*))
                           dlsym(h, "cuModuleGetFunction");
        auto setAttr_p = (CUresult(*)(CUfunction, CUfunction_attribute, int))
                             dlsym(h, "cuFuncSetAttribute");
        auto launchEx_p = (cuLaunchKernelEx_t)dlsym(h, "cuLaunchKernelEx");
        if (!cuInit_p || !devGet_p || !ctxRet_p || !ctxSet_p || !modLoad_p ||
            !getFn_p || !setAttr_p) {
            stage = 2;
            snprintf(elog, sizeof(elog), "dlsym miss");
            return false;
        }
        if (!launchEx_p) { stage = 10; snprintf(elog, sizeof(elog), "no cuLaunchKernelEx"); return false; }
        CUresult r;
        if ((r = cuInit_p(0)) != CUDA_SUCCESS) { stage = 3; rc = (int)r; return false; }
        CUdevice dev;
        if ((r = devGet_p(&dev, 0)) != CUDA_SUCCESS) { stage = 4; rc = (int)r; return false; }
        CUcontext ctx;
        if ((r = ctxRet_p(&ctx, dev)) != CUDA_SUCCESS) { stage = 5; rc = (int)r; return false; }
        if ((r = ctxSet_p(ctx)) != CUDA_SUCCESS) { stage = 6; rc = (int)r; return false; }
        CUjit_option opts[4] = {CU_JIT_ERROR_LOG_BUFFER,
                                CU_JIT_ERROR_LOG_BUFFER_SIZE_BYTES,
                                CU_JIT_INFO_LOG_BUFFER,
                                CU_JIT_INFO_LOG_BUFFER_SIZE_BYTES};
        void* vals[4] = {elog, (void*)(size_t)sizeof(elog),
                         ilog, (void*)(size_t)sizeof(ilog)};
        CUmodule mod;
        if ((r = modLoad_p(&mod, GEMM_PTX, 4, opts, vals)) != CUDA_SUCCESS) {
            stage = 7; rc = (int)r; return false;
        }
        CUfunction f;
        if ((r = getFn_p(&f, mod, "gemm_tc")) != CUDA_SUCCESS) {
            stage = 8; rc = (int)r; return false;
        }
        if ((r = setAttr_p(f, CU_FUNC_ATTRIBUTE_MAX_DYNAMIC_SHARED_SIZE_BYTES, SMEM_TC))
            != CUDA_SUCCESS) { stage = 9; rc = (int)r; return false; }
        fn = f;
        launchEx = launchEx_p;
        return true;
    }
    Jit() { ctor_ran = 1; try_init(); }
};
Jit g_jit;
}  // namespace

// ---------------------------------------------------------------------------
// Kernel 0: input-format detection (parallel).
// ---------------------------------------------------------------------------
__global__ void detect_kernel(const int* __restrict__ w,
                              const float* __restrict__ c2) {
    __shared__ int s_w_in_range;
    __shared__ int s_c2_scalelike;
    const int tid = threadIdx.x;
    if (tid == 0) { s_w_in_range = 1; s_c2_scalelike = 1; }
    __syncthreads();

    int bad_w = 0;
#pragma unroll
    for (int i = 0; i < 8; i++) {
        int v = w[tid + i * 256];
        if (v < -128 || v > 127) bad_w = 1;
    }
    float cv = c2[tid];
    int bad_c2 = !(cv > 0.0f && cv < 0.02f);

    if (__syncthreads_or(bad_w)) { if (tid == 0) s_w_in_range = 0; }
    if (__syncthreads_or(bad_c2)) { if (tid == 0) s_c2_scalelike = 0; }
    __syncthreads();
    if (tid == 0) {
        g_w_is_i32 = s_w_in_range;
        g_sb_swap = s_c2_scalelike ? 0 : 1;
    }
}

// ---------------------------------------------------------------------------
// Kernel 1: per-row dynamic quantization -> bf16, tiled+swizzled g_xb.
// ---------------------------------------------------------------------------
__global__ void quantize_rows_kernel(const float* __restrict__ x) {
    const int row = blockIdx.x;
    const int tid = threadIdx.x;

    const float4* xr = reinterpret_cast<const float4*>(x) + (size_t)row * (KDIM / 4);
    float4 v[4];
    float amax = 0.0f;
#pragma unroll
    for (int i = 0; i < 4; i++) {
        v[i] = xr[tid + i * 256];
        amax = fmaxf(amax, fmaxf(fmaxf(fabsf(v[i].x), fabsf(v[i].y)),
                                 fmaxf(fabsf(v[i].z), fabsf(v[i].w))));
    }
#pragma unroll
    for (int o = 16; o; o >>= 1)
        amax = fmaxf(amax, __shfl_xor_sync(0xFFFFFFFFu, amax, o));

    __shared__ float sm_[8];
    __shared__ float s_scale;
    if ((tid & 31) == 0) sm_[tid >> 5] = amax;
    __syncthreads();
    if (tid == 0) {
        float m = sm_[0];
#pragma unroll
        for (int i = 1; i < 8; i++) m = fmaxf(m, sm_[i]);
        float s = fmaxf(m / 127.0f, 1e-8f);
        g_ascale[row] = s;
        s_scale = s;
    }
    __syncthreads();

    const float inv = 1.0f / s_scale;
    const int mt = row >> 7, r = row & 127;
    const size_t mbase = ((size_t)mt * 64) << 14;
#pragma unroll
    for (int i = 0; i < 4; i++) {
        int q0 = max(-128, min(127, __float2int_rn(v[i].x * inv)));
        int q1 = max(-128, min(127, __float2int_rn(v[i].y * inv)));
        int q2 = max(-128, min(127, __float2int_rn(v[i].z * inv)));
        int q3 = max(-128, min(127, __float2int_rn(v[i].w * inv)));
        __nv_bfloat162 p0 = __floats2bfloat162_rn((float)q0, (float)q1);
        __nv_bfloat162 p1 = __floats2bfloat162_rn((float)q2, (float)q3);
        uint2 packed;
        packed.x = *reinterpret_cast<unsigned int*>(&p0);
        packed.y = *reinterpret_cast<unsigned int*>(&p1);
        int k = (tid + i * 256) * 4;
        int kt = k >> 6, c = k & 63;
        size_t addr = mbase + ((size_t)kt << 14) + SWZ(r * 128 + c * 2);
        *reinterpret_cast<uint2*>(g_xb + addr) = packed;
    }
}

// ---------------------------------------------------------------------------
// Kernel 2: transpose weight [K, N] -> bf16 tiled+swizzled g_wb [N, K] tiles.
// ---------------------------------------------------------------------------
__global__ void transpose_w_kernel(const void* __restrict__ wraw) {
    __shared__ uint8_t t[128][36];
    const int tid = threadIdx.x;
    const int n0 = blockIdx.x * 128;
    const int k0 = blockIdx.y * 32;

    if (g_w_is_i32) {
        const int* w = (const int*)wraw;
#pragma unroll
        for (int it = 0; it < 4; it++) {
            int i = tid + it * 256;
            int k = i >> 5, n4 = i & 31;
            int4 wv = *reinterpret_cast<const int4*>(
                w + (size_t)(k0 + k) * NDIM + n0 + n4 * 4);
            t[n4 * 4 + 0][k] = (uint8_t)wv.x;
            t[n4 * 4 + 1][k] = (uint8_t)wv.y;
            t[n4 * 4 + 2][k] = (uint8_t)wv.z;
            t[n4 * 4 + 3][k] = (uint8_t)wv.w;
        }
    } else {
        const int8_t* w = (const int8_t*)wraw;
#pragma unroll
        for (int it = 0; it < 4; it++) {
            int i = tid + it * 256;
            int k = i >> 5, n4 = i & 31;
            unsigned int wv = *reinterpret_cast<const unsigned int*>(
                w + (size_t)(k0 + k) * NDIM + n0 + n4 * 4);
            t[n4 * 4 + 0][k] = (uint8_t)(wv & 0xFF);
            t[n4 * 4 + 1][k] = (uint8_t)((wv >> 8) & 0xFF);
            t[n4 * 4 + 2][k] = (uint8_t)((wv >> 16) & 0xFF);
            t[n4 * 4 + 3][k] = (uint8_t)((wv >> 24) & 0xFF);
        }
    }
    __syncthreads();

    const int ntile = n0 >> 7;
#pragma unroll
    for (int it = 0; it < 4; it++) {
        int i = tid + it * 256;
        int n = i >> 3, kw = i & 7;
        float f0 = (float)(int8_t)t[n][kw * 4 + 0];
        float f1 = (float)(int8_t)t[n][kw * 4 + 1];
        float f2 = (float)(int8_t)t[n][kw * 4 + 2];
        float f3 = (float)(int8_t)t[n][kw * 4 + 3];
        __nv_bfloat162 p0 = __floats2bfloat162_rn(f0, f1);
        __nv_bfloat162 p1 = __floats2bfloat162_rn(f2, f3);
        uint2 packed;
        packed.x = *reinterpret_cast<unsigned int*>(&p0);
        packed.y = *reinterpret_cast<unsigned int*>(&p1);
        int kglob = k0 + kw * 4;
        int kt = kglob >> 6, c = kglob & 63;
        size_t addr = (((size_t)ntile * 64 + kt) << 14) + SWZ(n * 128 + c * 2);
        *reinterpret_cast<uint2*>(g_wb + addr) = packed;
    }
}

// ---------------------------------------------------------------------------
extern "C" void kernel_launch(void* const* d_in, const int* in_sizes, int n_in,
                              void* d_out, int out_size) {
    int idx_x = -1, idx_w = -1, idx_a = -1, idx_b = -1;
    for (int i = 0; i < n_in; i++) {
        long s = in_sizes[i];
        if (s == (long)MDIM * KDIM) idx_x = i;
        else if (s == (long)KDIM * NDIM) idx_w = i;
        else if (idx_a < 0) idx_a = i;
        else idx_b = i;
    }
    if (idx_x < 0 || idx_w < 0 || idx_a < 0 || idx_b < 0) {
        idx_x = 0; idx_w = 1; idx_a = 2; idx_b = 3;
    }

    const float* x  = (const float*)d_in[idx_x];
    const void*  wq = d_in[idx_w];
    const float* c2 = (const float*)d_in[idx_a];
    const float* c3 = (const float*)d_in[idx_b];
    float* out = (float*)d_out;

    static int static_init_ok = (g_jit.fn != nullptr) ? 1 : 0;
    if (!g_jit.fn) g_jit.try_init();

    if (!g_jit.fn) {
        fprintf(stderr,
                "JIT DIAG: ctor_ran=%d static_ok=%d stage=%d rc=%d\n"
                "--- error log ---\n%s\n--- info log ---\n%s\n",
                g_jit.ctor_ran, static_init_ok, g_jit.stage, g_jit.rc,
                g_jit.elog, g_jit.ilog);
        fflush(stderr);
        _Exit(3);
    }

    detect_kernel<<<1, 256>>>((const int*)wq, c2);
    quantize_rows_kernel<<<MDIM, 256>>>(x);
    transpose_w_kernel<<<dim3(NDIM / 128, KDIM / 32), 256>>>(wq);

    void *pa = nullptr, *pb = nullptr, *pasc = nullptr, *psb = nullptr;
    cudaGetSymbolAddress(&pa, g_xb);
    cudaGetSymbolAddress(&pb, g_wb);
    cudaGetSymbolAddress(&pasc, g_ascale);
    cudaGetSymbolAddress(&psb, g_sb_swap);
    void* pc2 = (void*)c2;
    void* pc3 = (void*)c3;
    void* pout = (void*)out;
    void* args[7] = {&pa, &pb, &pasc, &pc2, &pc3, &psb, &pout};

    // Persistent launch: 148 CTAs x 192 threads, per-thread default stream
    // (legacy stream would invalidate graph capture).
    CUlaunchConfig cfg;
    memset(&cfg, 0, sizeof(cfg));
    cfg.gridDimX = 148;
    cfg.gridDimY = 1;
    cfg.gridDimZ = 1;
    cfg.blockDimX = 192;
    cfg.blockDimY = 1;
    cfg.blockDimZ = 1;
    cfg.sharedMemBytes = SMEM_TC;
    cfg.hStream = (CUstream)0x2;  // CU_STREAM_PER_THREAD
    cfg.attrs = nullptr;
    cfg.numAttrs = 0;
    CUresult lr = g_jit.launchEx(&cfg, g_jit.fn, args, nullptr);
    if (lr != CUDA_SUCCESS) {
        fprintf(stderr, "LAUNCH DIAG: cuLaunchKernelEx rc=%d\n", (int)lr);
        fflush(stderr);
        _Exit(4);
    }
}